// round 3
// baseline (speedup 1.0000x reference)
#include <cuda_runtime.h>

#define NB 512
#define NS 16384
#define NFFT 16384
#define HFFT 8192
#define NT 512
#define SBUF_N 16896
#define SKEW(k) ((k) + ((k) >> 5))

// Global accumulators: 0=pearson(1-r) sum, 1=cos sum, 2=nmi sum, 3=|xp-tp| sum, 4=tp sum
__device__ double g_acc[5];
__device__ unsigned g_cnt;

struct Scr {
    double red[16];
    float  fred[16];
    int    hist[100];
    float  amaxv[16];
    int    amaxi[16];
    int    last;
};

// ---------------- small helpers ----------------
__device__ __forceinline__ float2 cmul(float2 a, float2 b) {
    return make_float2(a.x * b.x - a.y * b.y, a.x * b.y + a.y * b.x);
}

__device__ __forceinline__ int BR5(int x) {
    return ((x & 1) << 4) | ((x & 2) << 2) | (x & 4) | ((x & 8) >> 2) | ((x & 16) >> 4);
}
__device__ __forceinline__ int BR4(int x) {
    return ((x & 1) << 3) | ((x & 2) << 1) | ((x & 4) >> 1) | ((x & 8) >> 3);
}

// twiddle constants exp(-i*pi*e/16); switch form folds to immediates under full unroll
__device__ __forceinline__ float twc(int e) {
    switch (e & 15) {
        case 0:  return  1.0f;
        case 1:  return  0.980785280403f;
        case 2:  return  0.923879532511f;
        case 3:  return  0.831469612303f;
        case 4:  return  0.707106781187f;
        case 5:  return  0.555570233020f;
        case 6:  return  0.382683432365f;
        case 7:  return  0.195090322016f;
        case 8:  return  0.0f;
        case 9:  return -0.195090322016f;
        case 10: return -0.382683432365f;
        case 11: return -0.555570233020f;
        case 12: return -0.707106781187f;
        case 13: return -0.831469612303f;
        case 14: return -0.923879532511f;
        default: return -0.980785280403f;
    }
}
__device__ __forceinline__ float tws(int e) {
    switch (e & 15) {
        case 0:  return  0.0f;
        case 1:  return -0.195090322016f;
        case 2:  return -0.382683432365f;
        case 3:  return -0.555570233020f;
        case 4:  return -0.707106781187f;
        case 5:  return -0.831469612303f;
        case 6:  return -0.923879532511f;
        case 7:  return -0.980785280403f;
        case 8:  return -1.0f;
        case 9:  return -0.980785280403f;
        case 10: return -0.923879532511f;
        case 11: return -0.831469612303f;
        case 12: return -0.707106781187f;
        case 13: return -0.555570233020f;
        case 14: return -0.382683432365f;
        default: return -0.195090322016f;
    }
}

__device__ __forceinline__ void bfly(float2& p, float2& q, int e) {
    float c = twc(e), s = tws(e);
    float ax = p.x, ay = p.y, bx = q.x, by = q.y;
    p.x = ax + bx; p.y = ay + by;
    float dx = ax - bx, dy = ay - by;
    q.x = dx * c - dy * s;
    q.y = dx * s + dy * c;
}

// DIF radix-2 FFT of 32 register points. Output at position q = frequency brev5(q).
__device__ __forceinline__ void fft32(float2* v) {
#pragma unroll
    for (int h = 16; h >= 1; h >>= 1) {
#pragma unroll
        for (int g = 0; g < 32; g += 2 * h) {
#pragma unroll
            for (int j = 0; j < h; j++) {
                bfly(v[g + j], v[g + j + h], j * (16 / h));
            }
        }
    }
}

// DIF radix-2 FFT of 16 points. Output position q = frequency brev4(q).
__device__ __forceinline__ void fft16(float2* v) {
#pragma unroll
    for (int h = 8; h >= 1; h >>= 1) {
#pragma unroll
        for (int g = 0; g < 16; g += 2 * h) {
#pragma unroll
            for (int j = 0; j < h; j++) {
                bfly(v[g + j], v[g + j + h], j * (16 / h));
            }
        }
    }
}

// ---------------- 16384-pt FFT, 3 passes (32 x 32 x 16), 512 threads ----------------
// On entry: v[r] = input[tid + 512*r] (natural order).
// SCATTER=true : results written to sbuf[SKEW(k)] in natural frequency order.
// SCATTER=false: per-thread argmax of Re(X[k]) returned in (*bvp, *bip), min-index ties.
template <bool SCATTER>
__device__ __forceinline__ void fft16k(float2 (&v)[32], float2* __restrict__ sbuf, int tid,
                                       float* bvp, int* bip)
{
    __syncthreads();   // prior sbuf readers done before pass-1 stores

    // ---- pass 1: DFT_32 over stride-512, twiddle W_N^{t*j}, store [j][m] ----
    fft32(v);
    {
        float sp, cp;
        sincospif((float)tid * (1.0f / 8192.0f), &sp, &cp);
        float2 step = make_float2(cp, -sp);
        float2 w = make_float2(1.0f, 0.0f);
#pragma unroll
        for (int j = 0; j < 32; j++) {
            sbuf[j * 512 + tid] = cmul(v[BR5(j)], w);
            w = cmul(w, step);
        }
    }
    __syncthreads();

    // ---- pass 2: within each 512-block, DFT_32 over stride-16, twiddle W_512^{m2*j2} ----
    {
        int j = tid >> 4, m2 = tid & 15;
        int base = j * 512 + m2;
#pragma unroll
        for (int r2 = 0; r2 < 32; r2++) v[r2] = sbuf[base + 16 * r2];
        __syncthreads();
        fft32(v);
        float sp, cp;
        sincospif((float)m2 * (1.0f / 256.0f), &sp, &cp);
        float2 step = make_float2(cp, -sp);
        float2 w = make_float2(1.0f, 0.0f);
        int pbase = j * 32;
#pragma unroll
        for (int j2 = 0; j2 < 32; j2++) {
            sbuf[(pbase + j2) * 16 + (m2 ^ (j2 & 15))] = cmul(v[BR5(j2)], w);
            w = cmul(w, step);
        }
    }
    __syncthreads();

    // ---- pass 3: two 16-pt FFTs per thread (pairs p = tid, tid+512) ----
#pragma unroll
    for (int c = 0; c < 2; c++) {
        int p = tid + c * 512;
        int sw = p & 15;
#pragma unroll
        for (int m2 = 0; m2 < 16; m2++) v[c * 16 + m2] = sbuf[p * 16 + (m2 ^ sw)];
    }
    __syncthreads();
    fft16(v);
    fft16(v + 16);

    if (SCATTER) {
#pragma unroll
        for (int c = 0; c < 2; c++) {
            int p = tid + c * 512;
            int kb = (p >> 5) + 32 * (p & 31);
#pragma unroll
            for (int q = 0; q < 16; q++) {
                int k = kb + 1024 * BR4(q);
                sbuf[SKEW(k)] = v[c * 16 + q];
            }
        }
        __syncthreads();
    } else {
        float bv = -3.4e38f; int bi = 0;
#pragma unroll
        for (int c = 0; c < 2; c++) {
            int p = tid + c * 512;
            int kb = (p >> 5) + 32 * (p & 31);
#pragma unroll
            for (int q = 0; q < 16; q++) {
                int k = kb + 1024 * BR4(q);
                float re = v[c * 16 + q].x;
                if (re > bv || (re == bv && k < bi)) { bv = re; bi = k; }
            }
        }
        *bvp = bv; *bip = bi;
    }
}

// Hermitian unpack at arbitrary frequency j (mod N): returns (Xr, Xi, Tr, Ti)
__device__ __forceinline__ float4 unp(const float2* __restrict__ sbuf, int j) {
    int a = SKEW(j & (NFFT - 1));
    int c = SKEW((NFFT - j) & (NFFT - 1));
    float2 Z1 = sbuf[a], Z2 = sbuf[c];
    return make_float4(0.5f * (Z1.x + Z2.x),  0.5f * (Z1.y - Z2.y),
                       0.5f * (Z1.y + Z2.y), -0.5f * (Z1.x - Z2.x));
}

// ---------------- block reductions ----------------
__device__ double block_sum_d(double v, double* red, int tid) {
    __syncthreads();
    for (int o = 16; o; o >>= 1) v += __shfl_down_sync(0xffffffffu, v, o);
    if ((tid & 31) == 0) red[tid >> 5] = v;
    __syncthreads();
    if (tid == 0) {
        double w = red[0];
        for (int i = 1; i < 16; i++) w += red[i];
        red[0] = w;
    }
    __syncthreads();
    return red[0];
}

__device__ float block_min_f(float v, float* red, int tid) {
    __syncthreads();
    for (int o = 16; o; o >>= 1) v = fminf(v, __shfl_down_sync(0xffffffffu, v, o));
    if ((tid & 31) == 0) red[tid >> 5] = v;
    __syncthreads();
    if (tid == 0) {
        float w = red[0];
        for (int i = 1; i < 16; i++) w = fminf(w, red[i]);
        red[0] = w;
    }
    __syncthreads();
    return red[0];
}

__device__ float block_max_f(float v, float* red, int tid) {
    __syncthreads();
    for (int o = 16; o; o >>= 1) v = fmaxf(v, __shfl_down_sync(0xffffffffu, v, o));
    if ((tid & 31) == 0) red[tid >> 5] = v;
    __syncthreads();
    if (tid == 0) {
        float w = red[0];
        for (int i = 1; i < 16; i++) w = fmaxf(w, red[i]);
        red[0] = w;
    }
    __syncthreads();
    return red[0];
}

// ---------------- main per-row kernel ----------------
__global__ void __launch_bounds__(NT, 1)
row_kernel(const float* __restrict__ pred, const float* __restrict__ targ,
           const int* __restrict__ ip, const int* __restrict__ ep,
           float* __restrict__ out)
{
    extern __shared__ char smem[];
    float2* sbuf = (float2*)smem;
    Scr* scr = (Scr*)(smem + (size_t)SBUF_N * sizeof(float2));

    const int tid = threadIdx.x;
    const int b   = blockIdx.x;
    const int ii  = *ip;
    const float* x = pred + (size_t)ii * NB * NS + (size_t)b * NS;
    const float* y = targ + (size_t)b * NS;

    // ================= Phase 1: Pearson stats + min/max =================
    double sx = 0, sy = 0, sxy = 0, sxx = 0, syy = 0;
    float xmn = 3.4e38f, xmx = -3.4e38f, ymn = 3.4e38f, ymx = -3.4e38f;
    for (int n = tid; n < NS; n += NT) {
        float xv = x[n], yv = y[n];
        sx += xv; sy += yv;
        sxy += (double)xv * yv;
        sxx += (double)xv * xv;
        syy += (double)yv * yv;
        xmn = fminf(xmn, xv); xmx = fmaxf(xmx, xv);
        ymn = fminf(ymn, yv); ymx = fmaxf(ymx, yv);
    }
    sx  = block_sum_d(sx,  scr->red, tid);
    sy  = block_sum_d(sy,  scr->red, tid);
    sxy = block_sum_d(sxy, scr->red, tid);
    sxx = block_sum_d(sxx, scr->red, tid);
    syy = block_sum_d(syy, scr->red, tid);
    xmn = block_min_f(xmn, scr->fred, tid);
    xmx = block_max_f(xmx, scr->fred, tid);
    ymn = block_min_f(ymn, scr->fred, tid);
    ymx = block_max_f(ymx, scr->fred, tid);

    if (tid == 0) {
        // Per-row Pearson is invariant under the reference's global standardization.
        const double N = (double)NS;
        double num = N * sxy - sx * sy;
        double den = sqrt((N * sxx - sx * sx) * (N * syy - sy * sy));
        atomicAdd(&g_acc[0], 1.0 - num / den);
    }

    // ================= Phase 2: mutual information =================
    for (int c = tid; c < 100; c += NT) scr->hist[c] = 0;
    __syncthreads();
    {
        float bwx = __fdiv_rn(xmx - xmn, 10.0f);
        float bwy = __fdiv_rn(ymx - ymn, 10.0f);
        for (int n = tid; n < NS; n += NT) {
            int ix = (int)__fdiv_rn(x[n] - xmn, bwx);
            int iy = (int)__fdiv_rn(y[n] - ymn, bwy);
            ix = min(max(ix, 0), 9);
            iy = min(max(iy, 0), 9);
            atomicAdd(&scr->hist[ix * 10 + iy], 1);
        }
    }
    __syncthreads();
    if (tid == 0) {
        const float denom = 8388608.0f;  // B*S — faithful to reference normalization
        float hx[10], hy[10];
        for (int k = 0; k < 10; k++) { hx[k] = 0.f; hy[k] = 0.f; }
        for (int a = 0; a < 10; a++)
            for (int c = 0; c < 10; c++) {
                float h = (float)scr->hist[a * 10 + c];
                hx[a] += h; hy[c] += h;
            }
        float mi = 0.f;
        for (int a = 0; a < 10; a++) {
            float px = hx[a] / denom;
            for (int c = 0; c < 10; c++) {
                float py  = hy[c] / denom;
                float pxy = (float)scr->hist[a * 10 + c] / denom;
                mi += pxy * logf((pxy + 1e-8f) / (px * py + 1e-8f));
            }
        }
        float hxe = 0.f, hye = 0.f;
        for (int k = 0; k < 10; k++) {
            hxe -= (hx[k] / denom) * logf(hx[k] / denom + 1e-8f);
            hye -= (hy[k] / denom) * logf(hy[k] / denom + 1e-8f);
        }
        float nmi = mi / ((hxe + hye) * 0.5f);
        atomicAdd(&g_acc[2], (double)nmi);
    }

    // ================= Phase 3: single unwindowed FFT Z = FFT(x + i*y) =================
    float2 v[32];
#pragma unroll
    for (int r = 0; r < 32; r++) {
        int n = tid + 512 * r;
        v[r] = make_float2(x[n], y[n]);
    }
    float bv; int bi;
    fft16k<true>(v, sbuf, tid, &bv, &bi);   // natural-order spectrum in sbuf (skewed)

    // ---- Phase A (reads only): power spectrum + windowed phase-only spectrum C[k]
    // Hann window in frequency domain: Xw[k] = 0.5*X[k] - 0.25*(X[k-1] + X[k+1])  (exact).
    double pa = 0.0, pt = 0.0;
    {
        int t = 0;
        for (int k = tid; k <= HFFT; k += NT, t++) {
            float4 U  = unp(sbuf, k);
            float xp = U.x * U.x + U.y * U.y;
            float tp = U.z * U.z + U.w * U.w;
            pa += (double)fabsf(xp - tp);
            pt += (double)tp;

            float4 Um = unp(sbuf, k - 1);
            float4 Up = unp(sbuf, k + 1);
            float Xwr = 0.5f * U.x - 0.25f * (Um.x + Up.x);
            float Xwi = 0.5f * U.y - 0.25f * (Um.y + Up.y);
            float Twr = 0.5f * U.z - 0.25f * (Um.z + Up.z);
            float Twi = 0.5f * U.w - 0.25f * (Um.w + Up.w);
            float Cr = Xwr * Twr + Xwi * Twi;   // Xw * conj(Tw)
            float Ci = Xwi * Twr - Xwr * Twi;
            float inv = rsqrtf(Cr * Cr + Ci * Ci);
            v[t] = make_float2(Cr * inv, Ci * inv);
        }
    }
    __syncthreads();

    // ---- Phase B (writes): store D = conj(C) with Hermitian extension, in place.
    {
        int t = 0;
        for (int k = tid; k <= HFFT; k += NT, t++) {
            float2 C = v[t];
            sbuf[SKEW(k)]                        = make_float2(C.x, -C.y);  // conj(C[k])
            sbuf[SKEW((NFFT - k) & (NFFT - 1))]  = make_float2(C.x,  C.y);  // C[k] at N-k
        }
    }

    // power-spectrum reduction (leading syncthreads also orders Phase B writes)
    pa = block_sum_d(pa, scr->red, tid);
    pt = block_sum_d(pt, scr->red, tid);
    if (tid == 0) {
        atomicAdd(&g_acc[3], pa);
        atomicAdd(&g_acc[4], pt);
    }

    // ================= Phase 4: inverse FFT via forward FFT of conj, argmax =================
#pragma unroll
    for (int r = 0; r < 32; r++) v[r] = sbuf[SKEW(tid + 512 * r)];
    fft16k<false>(v, sbuf, tid, &bv, &bi);

    for (int o = 16; o; o >>= 1) {
        float ov = __shfl_down_sync(0xffffffffu, bv, o);
        int   oi = __shfl_down_sync(0xffffffffu, bi, o);
        if (ov > bv || (ov == bv && oi < bi)) { bv = ov; bi = oi; }
    }
    if ((tid & 31) == 0) { scr->amaxv[tid >> 5] = bv; scr->amaxi[tid >> 5] = bi; }
    __syncthreads();
    if (tid == 0) {
        for (int w2 = 1; w2 < 16; w2++) {
            float ov = scr->amaxv[w2]; int oi = scr->amaxi[w2];
            if (ov > bv || (ov == bv && oi < bi)) { bv = ov; bi = oi; }
        }
        atomicAdd(&g_acc[1], (double)cospif((float)bi * (1.0f / 8192.0f)));
    }

    // ================= Finalize: last block computes the loss and resets state =================
    if (tid == 0) {
        __threadfence();
        unsigned t = atomicAdd(&g_cnt, 1u);
        scr->last = (t == (unsigned)(NB - 1));
    }
    __syncthreads();
    if (scr->last && tid == 0) {
        __threadfence();
        double a0 = atomicAdd(&g_acc[0], 0.0);
        double a1 = atomicAdd(&g_acc[1], 0.0);
        double a2 = atomicAdd(&g_acc[2], 0.0);
        double a3 = atomicAdd(&g_acc[3], 0.0);
        double a4 = atomicAdd(&g_acc[4], 0.0);
        int e = *ep;
        double loss = a0 / (double)NB;
        if (e >= 400) {
            loss += 1.0 - a1 / (double)NB;   // phase correlation term
            loss += a3 / a4;                 // power spectrum (means over same count cancel)
        }
        if (e >= 700) {
            loss += 1.0 - a2 / (double)NB;   // mutual information term
        }
        out[0] = (float)loss;
        // reset accumulators for the next (graph-replayed) launch
        g_acc[0] = 0.0; g_acc[1] = 0.0; g_acc[2] = 0.0; g_acc[3] = 0.0; g_acc[4] = 0.0;
        __threadfence();
        g_cnt = 0u;
    }
}

extern "C" void kernel_launch(void* const* d_in, const int* in_sizes, int n_in,
                              void* d_out, int out_size) {
    const float* pred = (const float*)d_in[0];
    const float* targ = (const float*)d_in[1];
    const int*   ip   = (const int*)d_in[2];
    const int*   ep   = (const int*)d_in[3];
    float* out = (float*)d_out;

    size_t smem = (size_t)SBUF_N * sizeof(float2) + sizeof(Scr);
    cudaFuncSetAttribute(row_kernel, cudaFuncAttributeMaxDynamicSharedMemorySize, (int)smem);

    row_kernel<<<NB, NT, smem>>>(pred, targ, ip, ep, out);
}

// round 4
// speedup vs baseline: 1.6294x; 1.6294x over previous
#include <cuda_runtime.h>

#define NB 512
#define NS 16384
#define NFFT 16384
#define HFFT 8192
#define NT 512
#define SBUF_N 16896
#define SKEW(k) ((k) + ((k) >> 5))

// Global accumulators: 0=pearson(1-r) sum, 1=cos sum, 2=nmi sum, 3=|xp-tp| sum, 4=tp sum
__device__ double g_acc[5];
__device__ unsigned g_cnt;

struct Scr {
    double red[5][16];
    float  fmm[4][16];
    float  hxy[20];
    int    hist[100];
    float  amaxv[16];
    int    amaxi[16];
    float  bc[4];
    int    last;
};

// ---------------- small helpers ----------------
__device__ __forceinline__ float2 cmul(float2 a, float2 b) {
    return make_float2(a.x * b.x - a.y * b.y, a.x * b.y + a.y * b.x);
}

__device__ __forceinline__ int BR5(int x) {
    return ((x & 1) << 4) | ((x & 2) << 2) | (x & 4) | ((x & 8) >> 2) | ((x & 16) >> 4);
}
__device__ __forceinline__ int BR4(int x) {
    return ((x & 1) << 3) | ((x & 2) << 1) | ((x & 4) >> 1) | ((x & 8) >> 3);
}

// twiddle constants exp(-i*pi*e/16); switch form folds to immediates under full unroll
__device__ __forceinline__ float twc(int e) {
    switch (e & 15) {
        case 0:  return  1.0f;
        case 1:  return  0.980785280403f;
        case 2:  return  0.923879532511f;
        case 3:  return  0.831469612303f;
        case 4:  return  0.707106781187f;
        case 5:  return  0.555570233020f;
        case 6:  return  0.382683432365f;
        case 7:  return  0.195090322016f;
        case 8:  return  0.0f;
        case 9:  return -0.195090322016f;
        case 10: return -0.382683432365f;
        case 11: return -0.555570233020f;
        case 12: return -0.707106781187f;
        case 13: return -0.831469612303f;
        case 14: return -0.923879532511f;
        default: return -0.980785280403f;
    }
}
__device__ __forceinline__ float tws(int e) {
    switch (e & 15) {
        case 0:  return  0.0f;
        case 1:  return -0.195090322016f;
        case 2:  return -0.382683432365f;
        case 3:  return -0.555570233020f;
        case 4:  return -0.707106781187f;
        case 5:  return -0.831469612303f;
        case 6:  return -0.923879532511f;
        case 7:  return -0.980785280403f;
        case 8:  return -1.0f;
        case 9:  return -0.980785280403f;
        case 10: return -0.923879532511f;
        case 11: return -0.831469612303f;
        case 12: return -0.707106781187f;
        case 13: return -0.555570233020f;
        case 14: return -0.382683432365f;
        default: return -0.195090322016f;
    }
}

__device__ __forceinline__ void bfly(float2& p, float2& q, int e) {
    float c = twc(e), s = tws(e);
    float ax = p.x, ay = p.y, bx = q.x, by = q.y;
    p.x = ax + bx; p.y = ay + by;
    float dx = ax - bx, dy = ay - by;
    q.x = dx * c - dy * s;
    q.y = dx * s + dy * c;
}

// DIF radix-2 FFT of 32 register points. Output at position q = frequency brev5(q).
__device__ __forceinline__ void fft32(float2* v) {
#pragma unroll
    for (int h = 16; h >= 1; h >>= 1) {
#pragma unroll
        for (int g = 0; g < 32; g += 2 * h) {
#pragma unroll
            for (int j = 0; j < h; j++) {
                bfly(v[g + j], v[g + j + h], j * (16 / h));
            }
        }
    }
}

// DIF radix-2 FFT of 16 points. Output position q = frequency brev4(q).
__device__ __forceinline__ void fft16(float2* v) {
#pragma unroll
    for (int h = 8; h >= 1; h >>= 1) {
#pragma unroll
        for (int g = 0; g < 16; g += 2 * h) {
#pragma unroll
            for (int j = 0; j < h; j++) {
                bfly(v[g + j], v[g + j + h], j * (16 / h));
            }
        }
    }
}

// ---------------- 16384-pt FFT, 3 passes (32 x 32 x 16), 512 threads ----------------
template <bool SCATTER>
__device__ __forceinline__ void fft16k(float2 (&v)[32], float2* __restrict__ sbuf, int tid,
                                       float* bvp, int* bip)
{
    __syncthreads();   // prior sbuf readers done before pass-1 stores

    // ---- pass 1: DFT_32 over stride-512, twiddle W_N^{t*j}, store [j][m] ----
    fft32(v);
    {
        float sp, cp;
        sincospif((float)tid * (1.0f / 8192.0f), &sp, &cp);
        float2 step = make_float2(cp, -sp);
        float2 w = make_float2(1.0f, 0.0f);
#pragma unroll
        for (int j = 0; j < 32; j++) {
            sbuf[j * 512 + tid] = cmul(v[BR5(j)], w);
            w = cmul(w, step);
        }
    }
    __syncthreads();

    // ---- pass 2: within each 512-block, DFT_32 over stride-16, twiddle W_512^{m2*j2} ----
    {
        int j = tid >> 4, m2 = tid & 15;
        int base = j * 512 + m2;
#pragma unroll
        for (int r2 = 0; r2 < 32; r2++) v[r2] = sbuf[base + 16 * r2];
        __syncthreads();
        fft32(v);
        float sp, cp;
        sincospif((float)m2 * (1.0f / 256.0f), &sp, &cp);
        float2 step = make_float2(cp, -sp);
        float2 w = make_float2(1.0f, 0.0f);
        int pbase = j * 32;
#pragma unroll
        for (int j2 = 0; j2 < 32; j2++) {
            sbuf[(pbase + j2) * 16 + (m2 ^ (j2 & 15))] = cmul(v[BR5(j2)], w);
            w = cmul(w, step);
        }
    }
    __syncthreads();

    // ---- pass 3: two 16-pt FFTs per thread (pairs p = tid, tid+512) ----
#pragma unroll
    for (int c = 0; c < 2; c++) {
        int p = tid + c * 512;
        int sw = p & 15;
#pragma unroll
        for (int m2 = 0; m2 < 16; m2++) v[c * 16 + m2] = sbuf[p * 16 + (m2 ^ sw)];
    }
    __syncthreads();
    fft16(v);
    fft16(v + 16);

    if (SCATTER) {
#pragma unroll
        for (int c = 0; c < 2; c++) {
            int p = tid + c * 512;
            int kb = (p >> 5) + 32 * (p & 31);
#pragma unroll
            for (int q = 0; q < 16; q++) {
                int k = kb + 1024 * BR4(q);
                sbuf[SKEW(k)] = v[c * 16 + q];
            }
        }
        __syncthreads();
    } else {
        float bv = -3.4e38f; int bi = 0;
#pragma unroll
        for (int c = 0; c < 2; c++) {
            int p = tid + c * 512;
            int kb = (p >> 5) + 32 * (p & 31);
#pragma unroll
            for (int q = 0; q < 16; q++) {
                int k = kb + 1024 * BR4(q);
                float re = v[c * 16 + q].x;
                if (re > bv || (re == bv && k < bi)) { bv = re; bi = k; }
            }
        }
        *bvp = bv; *bip = bi;
    }
}

// Hermitian unpack at arbitrary frequency j (mod N): returns (Xr, Xi, Tr, Ti)
__device__ __forceinline__ float4 unp(const float2* __restrict__ sbuf, int j) {
    int a = SKEW(j & (NFFT - 1));
    int c = SKEW((NFFT - j) & (NFFT - 1));
    float2 Z1 = sbuf[a], Z2 = sbuf[c];
    return make_float4(0.5f * (Z1.x + Z2.x),  0.5f * (Z1.y - Z2.y),
                       0.5f * (Z1.y + Z2.y), -0.5f * (Z1.x - Z2.x));
}

// Stencil + phase-only correlation at frequency k. pa/pt accumulate power-spectrum terms.
__device__ __forceinline__ float2 phase_corr(const float2* __restrict__ sbuf, int k,
                                             double& pa, double& pt) {
    float4 U  = unp(sbuf, k);
    float xp = U.x * U.x + U.y * U.y;
    float tp = U.z * U.z + U.w * U.w;
    pa += (double)fabsf(xp - tp);
    pt += (double)tp;

    float4 Um = unp(sbuf, k - 1);
    float4 Up = unp(sbuf, k + 1);
    float Xwr = 0.5f * U.x - 0.25f * (Um.x + Up.x);
    float Xwi = 0.5f * U.y - 0.25f * (Um.y + Up.y);
    float Twr = 0.5f * U.z - 0.25f * (Um.z + Up.z);
    float Twi = 0.5f * U.w - 0.25f * (Um.w + Up.w);
    float Cr = Xwr * Twr + Xwi * Twi;   // Xw * conj(Tw)
    float Ci = Xwi * Twr - Xwr * Twi;
    float inv = rsqrtf(Cr * Cr + Ci * Ci);
    return make_float2(Cr * inv, Ci * inv);
}

// ---------------- main per-row kernel ----------------
__global__ void __launch_bounds__(NT, 1)
row_kernel(const float* __restrict__ pred, const float* __restrict__ targ,
           const int* __restrict__ ip, const int* __restrict__ ep,
           float* __restrict__ out)
{
    extern __shared__ char smem[];
    float2* sbuf = (float2*)smem;
    Scr* scr = (Scr*)(smem + (size_t)SBUF_N * sizeof(float2));

    const int tid  = threadIdx.x;
    const int lane = tid & 31;
    const int wid  = tid >> 5;
    const int b    = blockIdx.x;
    const int ii   = *ip;
    const float* x = pred + (size_t)ii * NB * NS + (size_t)b * NS;
    const float* y = targ + (size_t)b * NS;

    // ---- single global read of the row; feeds stats, MI, and FFT input ----
    float2 v[32];
#pragma unroll
    for (int r = 0; r < 32; r++) {
        int n = tid + 512 * r;
        v[r] = make_float2(x[n], y[n]);
    }

    // ================= Phase 1: Pearson stats + min/max (fused, 2 barriers) =================
    double sx = 0, sy = 0, sxy = 0, sxx = 0, syy = 0;
    float xmn = 3.4e38f, xmx = -3.4e38f, ymn = 3.4e38f, ymx = -3.4e38f;
#pragma unroll
    for (int r = 0; r < 32; r++) {
        float xv = v[r].x, yv = v[r].y;
        sx += xv; sy += yv;
        sxy += (double)xv * yv;
        sxx += (double)xv * xv;
        syy += (double)yv * yv;
        xmn = fminf(xmn, xv); xmx = fmaxf(xmx, xv);
        ymn = fminf(ymn, yv); ymx = fmaxf(ymx, yv);
    }
#pragma unroll
    for (int o = 16; o; o >>= 1) {
        sx  += __shfl_down_sync(0xffffffffu, sx,  o);
        sy  += __shfl_down_sync(0xffffffffu, sy,  o);
        sxy += __shfl_down_sync(0xffffffffu, sxy, o);
        sxx += __shfl_down_sync(0xffffffffu, sxx, o);
        syy += __shfl_down_sync(0xffffffffu, syy, o);
        xmn = fminf(xmn, __shfl_down_sync(0xffffffffu, xmn, o));
        xmx = fmaxf(xmx, __shfl_down_sync(0xffffffffu, xmx, o));
        ymn = fminf(ymn, __shfl_down_sync(0xffffffffu, ymn, o));
        ymx = fmaxf(ymx, __shfl_down_sync(0xffffffffu, ymx, o));
    }
    if (lane == 0) {
        scr->red[0][wid] = sx;  scr->red[1][wid] = sy;  scr->red[2][wid] = sxy;
        scr->red[3][wid] = sxx; scr->red[4][wid] = syy;
        scr->fmm[0][wid] = xmn; scr->fmm[1][wid] = xmx;
        scr->fmm[2][wid] = ymn; scr->fmm[3][wid] = ymx;
    }
    // zero MI histogram while the reduction settles (disjoint addresses)
    for (int c = tid; c < 100; c += NT) scr->hist[c] = 0;
    __syncthreads();
    if (tid < 32) {
        bool a = (lane < 16);
        double r0 = a ? scr->red[0][lane] : 0.0;
        double r1 = a ? scr->red[1][lane] : 0.0;
        double r2 = a ? scr->red[2][lane] : 0.0;
        double r3 = a ? scr->red[3][lane] : 0.0;
        double r4 = a ? scr->red[4][lane] : 0.0;
        float m0 = a ? scr->fmm[0][lane] :  3.4e38f;
        float m1 = a ? scr->fmm[1][lane] : -3.4e38f;
        float m2 = a ? scr->fmm[2][lane] :  3.4e38f;
        float m3 = a ? scr->fmm[3][lane] : -3.4e38f;
#pragma unroll
        for (int o = 16; o; o >>= 1) {
            r0 += __shfl_down_sync(0xffffffffu, r0, o);
            r1 += __shfl_down_sync(0xffffffffu, r1, o);
            r2 += __shfl_down_sync(0xffffffffu, r2, o);
            r3 += __shfl_down_sync(0xffffffffu, r3, o);
            r4 += __shfl_down_sync(0xffffffffu, r4, o);
            m0 = fminf(m0, __shfl_down_sync(0xffffffffu, m0, o));
            m1 = fmaxf(m1, __shfl_down_sync(0xffffffffu, m1, o));
            m2 = fminf(m2, __shfl_down_sync(0xffffffffu, m2, o));
            m3 = fmaxf(m3, __shfl_down_sync(0xffffffffu, m3, o));
        }
        if (lane == 0) {
            const double N = (double)NS;
            double num = N * r2 - r0 * r1;
            double den = sqrt((N * r3 - r0 * r0) * (N * r4 - r1 * r1));
            atomicAdd(&g_acc[0], 1.0 - num / den);
            scr->bc[0] = m0; scr->bc[1] = m1; scr->bc[2] = m2; scr->bc[3] = m3;
        }
    }
    __syncthreads();
    xmn = scr->bc[0]; xmx = scr->bc[1]; ymn = scr->bc[2]; ymx = scr->bc[3];

    // ================= Phase 2: mutual information =================
    {
        float bwx = __fdiv_rn(xmx - xmn, 10.0f);
        float bwy = __fdiv_rn(ymx - ymn, 10.0f);
#pragma unroll
        for (int r = 0; r < 32; r++) {
            int ix = (int)__fdiv_rn(v[r].x - xmn, bwx);
            int iy = (int)__fdiv_rn(v[r].y - ymn, bwy);
            ix = min(max(ix, 0), 9);
            iy = min(max(iy, 0), 9);
            atomicAdd(&scr->hist[ix * 10 + iy], 1);
        }
    }
    __syncthreads();
    if (tid < 32) {
        const float denom = 8388608.0f;  // B*S — faithful to reference normalization
        float rs = 0.f;
        if (lane < 10) {
#pragma unroll
            for (int c = 0; c < 10; c++) rs += (float)scr->hist[lane * 10 + c];
            scr->hxy[lane] = rs;
        } else if (lane < 20) {
            int c = lane - 10;
#pragma unroll
            for (int a = 0; a < 10; a++) rs += (float)scr->hist[a * 10 + c];
            scr->hxy[lane] = rs;
        }
        __syncwarp();
        float mi = 0.f;
#pragma unroll
        for (int u = 0; u < 4; u++) {
            int l = lane + 32 * u;
            if (l < 100) {
                int a2 = l / 10, c2 = l - 10 * a2;
                float px  = scr->hxy[a2] / denom;
                float py  = scr->hxy[10 + c2] / denom;
                float pxy = (float)scr->hist[l] / denom;
                mi += pxy * logf((pxy + 1e-8f) / (px * py + 1e-8f));
            }
        }
        float he = 0.f;
        if (lane < 20) {
            float p = scr->hxy[lane] / denom;
            he = -p * logf(p + 1e-8f);
        }
#pragma unroll
        for (int o = 16; o; o >>= 1) {
            mi += __shfl_down_sync(0xffffffffu, mi, o);
            he += __shfl_down_sync(0xffffffffu, he, o);
        }
        if (lane == 0) atomicAdd(&g_acc[2], (double)(mi / (he * 0.5f)));
    }

    // ================= Phase 3: single unwindowed FFT Z = FFT(x + i*y) =================
    float bv; int bi;
    fft16k<true>(v, sbuf, tid, &bv, &bi);   // natural-order spectrum in sbuf (skewed)

    // ---- Phase A (reads only, constant register indices): power spectrum +
    //      frequency-domain Hann (Xw[k] = 0.5 X[k] - 0.25(X[k-1]+X[k+1]), exact) + phase-only C
    double pa = 0.0, pt = 0.0;
#pragma unroll
    for (int r = 0; r < 16; r++) {
        v[r] = phase_corr(sbuf, tid + 512 * r, pa, pt);
    }
    float2 c81 = make_float2(0.f, 0.f);
    if (tid == 0) c81 = phase_corr(sbuf, HFFT, pa, pt);   // k = 8192 (self-conjugate, Ci = 0 exactly)
    __syncthreads();

    // ---- Phase B (writes): store D = conj(C) with Hermitian extension, in place.
#pragma unroll
    for (int r = 0; r < 16; r++) {
        int k = tid + 512 * r;
        float2 C = v[r];
        sbuf[SKEW(k)]                       = make_float2(C.x, -C.y);  // conj(C[k])
        sbuf[SKEW((NFFT - k) & (NFFT - 1))] = make_float2(C.x,  C.y);  // C[k] at N-k
    }
    if (tid == 0) sbuf[SKEW(HFFT)] = make_float2(c81.x, -c81.y);

    // power-spectrum reduction (its barrier also orders Phase B writes before fft#2 loads)
#pragma unroll
    for (int o = 16; o; o >>= 1) {
        pa += __shfl_down_sync(0xffffffffu, pa, o);
        pt += __shfl_down_sync(0xffffffffu, pt, o);
    }
    if (lane == 0) { scr->red[0][wid] = pa; scr->red[1][wid] = pt; }
    __syncthreads();
    if (tid < 32) {
        double p0 = (lane < 16) ? scr->red[0][lane] : 0.0;
        double p1 = (lane < 16) ? scr->red[1][lane] : 0.0;
#pragma unroll
        for (int o = 16; o; o >>= 1) {
            p0 += __shfl_down_sync(0xffffffffu, p0, o);
            p1 += __shfl_down_sync(0xffffffffu, p1, o);
        }
        if (lane == 0) {
            atomicAdd(&g_acc[3], p0);
            atomicAdd(&g_acc[4], p1);
        }
    }

    // ================= Phase 4: inverse FFT via forward FFT of conj, argmax =================
#pragma unroll
    for (int r = 0; r < 32; r++) v[r] = sbuf[SKEW(tid + 512 * r)];
    fft16k<false>(v, sbuf, tid, &bv, &bi);

    for (int o = 16; o; o >>= 1) {
        float ov = __shfl_down_sync(0xffffffffu, bv, o);
        int   oi = __shfl_down_sync(0xffffffffu, bi, o);
        if (ov > bv || (ov == bv && oi < bi)) { bv = ov; bi = oi; }
    }
    if (lane == 0) { scr->amaxv[wid] = bv; scr->amaxi[wid] = bi; }
    __syncthreads();
    if (tid == 0) {
        for (int w2 = 1; w2 < 16; w2++) {
            float ov = scr->amaxv[w2]; int oi = scr->amaxi[w2];
            if (ov > bv || (ov == bv && oi < bi)) { bv = ov; bi = oi; }
        }
        atomicAdd(&g_acc[1], (double)cospif((float)bi * (1.0f / 8192.0f)));
    }

    // ================= Finalize: last block computes the loss and resets state =================
    if (tid == 0) {
        __threadfence();
        unsigned t = atomicAdd(&g_cnt, 1u);
        scr->last = (t == (unsigned)(NB - 1));
    }
    __syncthreads();
    if (scr->last && tid == 0) {
        __threadfence();
        double a0 = atomicAdd(&g_acc[0], 0.0);
        double a1 = atomicAdd(&g_acc[1], 0.0);
        double a2 = atomicAdd(&g_acc[2], 0.0);
        double a3 = atomicAdd(&g_acc[3], 0.0);
        double a4 = atomicAdd(&g_acc[4], 0.0);
        int e = *ep;
        double loss = a0 / (double)NB;
        if (e >= 400) {
            loss += 1.0 - a1 / (double)NB;   // phase correlation term
            loss += a3 / a4;                 // power spectrum (means over same count cancel)
        }
        if (e >= 700) {
            loss += 1.0 - a2 / (double)NB;   // mutual information term
        }
        out[0] = (float)loss;
        // reset accumulators for the next (graph-replayed) launch
        g_acc[0] = 0.0; g_acc[1] = 0.0; g_acc[2] = 0.0; g_acc[3] = 0.0; g_acc[4] = 0.0;
        __threadfence();
        g_cnt = 0u;
    }
}

extern "C" void kernel_launch(void* const* d_in, const int* in_sizes, int n_in,
                              void* d_out, int out_size) {
    const float* pred = (const float*)d_in[0];
    const float* targ = (const float*)d_in[1];
    const int*   ip   = (const int*)d_in[2];
    const int*   ep   = (const int*)d_in[3];
    float* out = (float*)d_out;

    size_t smem = (size_t)SBUF_N * sizeof(float2) + sizeof(Scr);
    cudaFuncSetAttribute(row_kernel, cudaFuncAttributeMaxDynamicSharedMemorySize, (int)smem);

    row_kernel<<<NB, NT, smem>>>(pred, targ, ip, ep, out);
}